// round 5
// baseline (speedup 1.0000x reference)
#include <cuda_runtime.h>
#include <cuda_bf16.h>
#include <cstdint>

#define DM 1024
#define DI 2048
#define DS 16
#define Mrows 4096
#define Lseq 2048

// ---------------- scratch (device globals; allocation-free) ----------------
__device__ float g_U[Mrows * DI];
__device__ float g_S[Mrows * DI];
__device__ float g_DELTA[Mrows * DI];
__device__ float g_BM[Mrows * DS];
__device__ float g_CM[Mrows * DS];
__device__ __nv_bfloat16 g_Uh[Mrows * DI], g_Ul[Mrows * DI];
__device__ __nv_bfloat16 g_Yh[Mrows * DI], g_Yl[Mrows * DI];
__device__ __nv_bfloat16 g_xh[Mrows * DM], g_xl[Mrows * DM];
__device__ __nv_bfloat16 g_WinTh[2 * DI * DM], g_WinTl[2 * DI * DM]; // [4096][1024]
__device__ __nv_bfloat16 g_WdTh[DI * DI], g_WdTl[DI * DI];           // [2048][2048]
__device__ __nv_bfloat16 g_WoTh[DM * DI], g_WoTl[DM * DI];           // [1024][2048]

// ---------------- helpers ----------------
__device__ __forceinline__ float siluf(float x) { return x / (1.0f + __expf(-x)); }
__device__ __forceinline__ float softplusf(float x) {
    return (x > 20.0f) ? x : log1pf(__expf(x));
}
__device__ __forceinline__ uint32_t smem_u32(const void* p) {
    uint32_t a;
    asm("{ .reg .u64 t; cvta.to.shared.u64 t, %1; cvt.u32.u64 %0, t; }" : "=r"(a) : "l"(p));
    return a;
}
__device__ __forceinline__ void cpa16(uint32_t s, const void* g) {
    asm volatile("cp.async.cg.shared.global [%0], [%1], 16;" :: "r"(s), "l"(g));
}
__device__ __forceinline__ void cpa_commit() { asm volatile("cp.async.commit_group;"); }

__device__ __forceinline__ void ldsm4(uint32_t* r, uint32_t addr) {
    asm volatile("ldmatrix.sync.aligned.m8n8.x4.shared.b16 {%0,%1,%2,%3}, [%4];"
                 : "=r"(r[0]), "=r"(r[1]), "=r"(r[2]), "=r"(r[3]) : "r"(addr));
}
__device__ __forceinline__ void mma16816(float* d, const uint32_t* a, const uint32_t* b) {
    asm volatile(
        "mma.sync.aligned.m16n8k16.row.col.f32.bf16.bf16.f32 "
        "{%0,%1,%2,%3}, {%4,%5,%6,%7}, {%8,%9}, {%0,%1,%2,%3};\n"
        : "+f"(d[0]), "+f"(d[1]), "+f"(d[2]), "+f"(d[3])
        : "r"(a[0]), "r"(a[1]), "r"(a[2]), "r"(a[3]), "r"(b[0]), "r"(b[1]));
}

// SMEM geometry: 4 tiles per stage, each 128 rows x 32 bf16 (64B data),
// padded to 80B per row (16B-aligned; 80*r mod 128 distinct for r=0..7 ->
// conflict-free ldmatrix).
#define TPAD 80                 // bytes per row
#define TILE_B (128 * TPAD)     // 10240 bytes per tile
#define STAGE_B (4 * TILE_B)    // 40960 bytes per stage
#define NSTAGE 4
#define SMEM_TOT (NSTAGE * STAGE_B)  // 163840

// ---------------------------------------------------------------------------
// load one K-chunk (32 cols) of 4 bf16 tiles into SMEM stage base `sb`
// tiles: 0=Ah 1=Al 2=Bh 3=Bl ; rows: A from m0, B from n0 ; all k-contiguous
// Always commits a group (possibly empty) to keep wait_group counting uniform.
// ---------------------------------------------------------------------------
__device__ __forceinline__ void load_chunk(
    const __nv_bfloat16* __restrict__ Ah, const __nv_bfloat16* __restrict__ Al,
    const __nv_bfloat16* __restrict__ Bh, const __nv_bfloat16* __restrict__ Bl,
    int m0, int n0, int kc, int Kdim, uint32_t sb, int tid, bool active)
{
    if (active) {
        const int tile = tid >> 6;     // 0..3
        const int idx  = tid & 63;
        const __nv_bfloat16* base;
        int r0;
        if (tile == 0)      { base = Ah; r0 = m0; }
        else if (tile == 1) { base = Al; r0 = m0; }
        else if (tile == 2) { base = Bh; r0 = n0; }
        else                { base = Bl; r0 = n0; }
        const uint32_t dst0 = sb + (uint32_t)tile * TILE_B;
#pragma unroll
        for (int j = 0; j < 8; ++j) {
            const int c = j * 64 + idx;      // 0..511
            const int row = c >> 2;
            const int col16 = c & 3;         // 16B chunk within 64B row
            const __nv_bfloat16* src = base + (size_t)(r0 + row) * Kdim + kc + col16 * 8;
            cpa16(dst0 + (uint32_t)(row * TPAD + col16 * 16), (const void*)src);
        }
    }
    cpa_commit();
}

// ---------------------------------------------------------------------------
// HMMA bf16-split GEMM: C[M,N] = A[M,K] * B[N,K]^T  (fp32 accum)
// C ~= Ah*Bh + Ah*Bl + Al*Bh. Block 128x128, K-chunk 32, 4-stage cp.async.
// 8 warps (4m x 2n), warp tile 32x64.
// MODE 0: n0<2048 -> U=silu -> out0 fp32 + (obh,obl) bf16 split; else S=silu -> out1
// MODE 1: softplus(c + bias[n]) -> out0
// MODE 2: plain -> out0
// ---------------------------------------------------------------------------
template <int MODE>
__global__ void __launch_bounds__(256, 1)
tgemm(const __nv_bfloat16* __restrict__ Ah, const __nv_bfloat16* __restrict__ Al,
      const __nv_bfloat16* __restrict__ Bh, const __nv_bfloat16* __restrict__ Bl,
      int Kdim, int ostride,
      const float* __restrict__ bias,
      float* __restrict__ out0, float* __restrict__ out1,
      __nv_bfloat16* __restrict__ obh, __nv_bfloat16* __restrict__ obl)
{
    extern __shared__ char smem[];
    const uint32_t sb = smem_u32(smem);

    const int tid  = threadIdx.x;
    const int lane = tid & 31;
    const int wid  = tid >> 5;
    const int wm   = wid & 3;   // 0..3 (m)
    const int wn   = wid >> 2;  // 0..1 (n)
    const int m0 = blockIdx.y * 128;
    const int n0 = blockIdx.x * 128;

    // ldmatrix per-lane offsets (byte offsets within a tile)
    const uint32_t a_off =
        (uint32_t)(wm * 32 + (lane & 15)) * TPAD + (uint32_t)((lane >> 4) * 16);
    const int p = lane >> 3; // 0..3
    const uint32_t b_off =
        (uint32_t)(wn * 64 + (p >> 1) * 8 + (lane & 7)) * TPAD + (uint32_t)((p & 1) * 16);

    float acc[2][8][4];
#pragma unroll
    for (int i = 0; i < 2; ++i)
#pragma unroll
        for (int j = 0; j < 8; ++j)
#pragma unroll
            for (int q = 0; q < 4; ++q) acc[i][j][q] = 0.0f;

    const int NC = Kdim >> 5;

    // prologue: prefetch chunks 0..2
#pragma unroll
    for (int s = 0; s < NSTAGE - 1; ++s)
        load_chunk(Ah, Al, Bh, Bl, m0, n0, s * 32, Kdim,
                   sb + (uint32_t)s * STAGE_B, tid, s < NC);

    for (int c = 0; c < NC; ++c) {
        // chunk c resident once <=2 newer groups remain pending
        asm volatile("cp.async.wait_group 2;" ::: "memory");
        __syncthreads();

        // prefetch chunk c+3 into stage (c+3)&3 (previous compute done per barrier)
        load_chunk(Ah, Al, Bh, Bl, m0, n0, (c + NSTAGE - 1) * 32, Kdim,
                   sb + (uint32_t)((c + NSTAGE - 1) & (NSTAGE - 1)) * STAGE_B, tid,
                   (c + NSTAGE - 1) < NC);

        const uint32_t st = sb + (uint32_t)(c & (NSTAGE - 1)) * STAGE_B;
        const uint32_t smAh = st;
        const uint32_t smAl = st + TILE_B;
        const uint32_t smBh = st + 2 * TILE_B;
        const uint32_t smBl = st + 3 * TILE_B;

#pragma unroll
        for (int k16 = 0; k16 < 2; ++k16) {
            const uint32_t kb = (uint32_t)(k16 * 32);
            uint32_t ah[2][4], al[2][4], bh[4][4], bl[4][4];
#pragma unroll
            for (int mt = 0; mt < 2; ++mt) {
                ldsm4(ah[mt], smAh + kb + a_off + (uint32_t)(mt * 16 * TPAD));
                ldsm4(al[mt], smAl + kb + a_off + (uint32_t)(mt * 16 * TPAD));
            }
#pragma unroll
            for (int p2 = 0; p2 < 4; ++p2) {
                ldsm4(bh[p2], smBh + kb + b_off + (uint32_t)(p2 * 16 * TPAD));
                ldsm4(bl[p2], smBl + kb + b_off + (uint32_t)(p2 * 16 * TPAD));
            }
#pragma unroll
            for (int mt = 0; mt < 2; ++mt) {
#pragma unroll
                for (int nt = 0; nt < 8; ++nt) {
                    const uint32_t* bfh = &bh[nt >> 1][(nt & 1) * 2];
                    const uint32_t* bfl = &bl[nt >> 1][(nt & 1) * 2];
                    mma16816(acc[mt][nt], ah[mt], bfh);
                    mma16816(acc[mt][nt], ah[mt], bfl);
                    mma16816(acc[mt][nt], al[mt], bfh);
                }
            }
        }
        __syncthreads();
    }

    // ---------------- epilogue ----------------
    const int g2 = lane >> 2;        // 0..7 (row within 8)
    const int c2 = (lane & 3) * 2;   // col pair
#pragma unroll
    for (int mt = 0; mt < 2; ++mt) {
        const int r0 = m0 + wm * 32 + mt * 16 + g2;
#pragma unroll
        for (int nt = 0; nt < 8; ++nt) {
            const int col = n0 + wn * 64 + nt * 8 + c2;
            float v0 = acc[mt][nt][0], v1 = acc[mt][nt][1];
            float v2 = acc[mt][nt][2], v3 = acc[mt][nt][3];

            if (MODE == 0) {
                v0 = siluf(v0); v1 = siluf(v1); v2 = siluf(v2); v3 = siluf(v3);
                if (n0 < 2048) {
                    *(float2*)(out0 + (size_t)r0 * 2048 + col)       = make_float2(v0, v1);
                    *(float2*)(out0 + (size_t)(r0 + 8) * 2048 + col) = make_float2(v2, v3);
                    __nv_bfloat162 h0, l0, h1, l1;
                    h0.x = __float2bfloat16(v0); h0.y = __float2bfloat16(v1);
                    l0.x = __float2bfloat16(v0 - __bfloat162float(h0.x));
                    l0.y = __float2bfloat16(v1 - __bfloat162float(h0.y));
                    h1.x = __float2bfloat16(v2); h1.y = __float2bfloat16(v3);
                    l1.x = __float2bfloat16(v2 - __bfloat162float(h1.x));
                    l1.y = __float2bfloat16(v3 - __bfloat162float(h1.y));
                    *(__nv_bfloat162*)(obh + (size_t)r0 * 2048 + col)       = h0;
                    *(__nv_bfloat162*)(obl + (size_t)r0 * 2048 + col)       = l0;
                    *(__nv_bfloat162*)(obh + (size_t)(r0 + 8) * 2048 + col) = h1;
                    *(__nv_bfloat162*)(obl + (size_t)(r0 + 8) * 2048 + col) = l1;
                } else {
                    const int cs = col - 2048;
                    *(float2*)(out1 + (size_t)r0 * 2048 + cs)       = make_float2(v0, v1);
                    *(float2*)(out1 + (size_t)(r0 + 8) * 2048 + cs) = make_float2(v2, v3);
                }
            } else if (MODE == 1) {
                const float b0 = bias[col], b1 = bias[col + 1];
                *(float2*)(out0 + (size_t)r0 * ostride + col) =
                    make_float2(softplusf(v0 + b0), softplusf(v1 + b1));
                *(float2*)(out0 + (size_t)(r0 + 8) * ostride + col) =
                    make_float2(softplusf(v2 + b0), softplusf(v3 + b1));
            } else {
                *(float2*)(out0 + (size_t)r0 * ostride + col)       = make_float2(v0, v1);
                *(float2*)(out0 + (size_t)(r0 + 8) * ostride + col) = make_float2(v2, v3);
            }
        }
    }
}

// ---------------------------------------------------------------------------
// weight transpose + bf16 split: in[K][N] fp32 -> oh/ol [N][K] bf16
// ---------------------------------------------------------------------------
__global__ void __launch_bounds__(256)
transp_split(const float* __restrict__ in, __nv_bfloat16* __restrict__ oh,
             __nv_bfloat16* __restrict__ ol, int K, int N)
{
    __shared__ float t[32][33];
    const int n0 = blockIdx.x * 32, k0 = blockIdx.y * 32;
    const int tx = threadIdx.x & 31, ty = threadIdx.x >> 5; // 32 x 8
#pragma unroll
    for (int i = 0; i < 32; i += 8)
        t[ty + i][tx] = in[(size_t)(k0 + ty + i) * N + n0 + tx];
    __syncthreads();
#pragma unroll
    for (int i = 0; i < 32; i += 8) {
        float v = t[tx][ty + i];
        const int n = n0 + ty + i, k = k0 + tx;
        __nv_bfloat16 h = __float2bfloat16(v);
        oh[(size_t)n * K + k] = h;
        ol[(size_t)n * K + k] = __float2bfloat16(v - __bfloat162float(h));
    }
}

// x -> bf16 hi/lo (elementwise)
__global__ void __launch_bounds__(256)
split_x_k(const float* __restrict__ x, __nv_bfloat16* __restrict__ xh,
          __nv_bfloat16* __restrict__ xl)
{
    const int i = blockIdx.x * 256 + threadIdx.x;
    float4 v = ((const float4*)x)[i];
    __nv_bfloat162 hh0, hh1, ll0, ll1;
    hh0.x = __float2bfloat16(v.x); hh0.y = __float2bfloat16(v.y);
    hh1.x = __float2bfloat16(v.z); hh1.y = __float2bfloat16(v.w);
    ll0.x = __float2bfloat16(v.x - __bfloat162float(hh0.x));
    ll0.y = __float2bfloat16(v.y - __bfloat162float(hh0.y));
    ll1.x = __float2bfloat16(v.z - __bfloat162float(hh1.x));
    ll1.y = __float2bfloat16(v.w - __bfloat162float(hh1.y));
    ((__nv_bfloat162*)xh)[2*i]   = hh0;
    ((__nv_bfloat162*)xh)[2*i+1] = hh1;
    ((__nv_bfloat162*)xl)[2*i]   = ll0;
    ((__nv_bfloat162*)xl)[2*i+1] = ll1;
}

// ---------------------------------------------------------------------------
// Bm = U @ W_B, Cm = U @ W_C (fp32 SIMT, K=2048, N=16 each)
// ---------------------------------------------------------------------------
__global__ void __launch_bounds__(256)
bc_k(const float* __restrict__ U,
     const float* __restrict__ WB, const float* __restrict__ WC,
     float* __restrict__ BMo, float* __restrict__ CMo)
{
    const int tid = threadIdx.x;
    const int n = tid & 31;
    const int r = tid >> 5;
    const int m = blockIdx.x * 8 + r;

    const float* Wp = (n < DS) ? (WB + n) : (WC + (n - DS));
    const float* Up = U + (size_t)m * DI;

    float acc = 0.0f;
#pragma unroll 8
    for (int k = 0; k < DI; ++k)
        acc = fmaf(Up[k], Wp[(size_t)k * DS], acc);

    if (n < DS) BMo[(size_t)m * DS + n] = acc;
    else        CMo[(size_t)m * DS + (n - DS)] = acc;
}

// ---------------------------------------------------------------------------
// Sequential selective scan; emits Y as bf16 hi/lo (input for final GEMM)
// ---------------------------------------------------------------------------
__global__ void __launch_bounds__(64)
scan_k(const float* __restrict__ DEL, const float* __restrict__ U,
       const float* __restrict__ S,
       const float* __restrict__ BMi, const float* __restrict__ CMi,
       const float* __restrict__ Alog, const float* __restrict__ Dp,
       __nv_bfloat16* __restrict__ Yh, __nv_bfloat16* __restrict__ Yl)
{
    const int tid = threadIdx.x;
    const int g = blockIdx.x * 16 + (tid >> 2);
    const int b = g >> 11;
    const int d = g & (DI - 1);
    const int sub = tid & 3;

    const float A0 = -__expf(Alog[d * DS + sub * 4 + 0]);
    const float A1 = -__expf(Alog[d * DS + sub * 4 + 1]);
    const float A2 = -__expf(Alog[d * DS + sub * 4 + 2]);
    const float A3 = -__expf(Alog[d * DS + sub * 4 + 3]);
    const float Dd = Dp[d];

    float h0 = 0.f, h1 = 0.f, h2 = 0.f, h3 = 0.f;
    size_t xbase = ((size_t)b * Lseq) * DI + d;
    size_t rbase = ((size_t)b * Lseq) * DS + sub * 4;

#pragma unroll 4
    for (int t = 0; t < Lseq; ++t) {
        const float delta = DEL[xbase];
        const float uu    = U[xbase];
        const float4 Bv = *(const float4*)(BMi + rbase);
        const float4 Cv = *(const float4*)(CMi + rbase);

        const float a0 = __expf(delta * A0);
        const float a1 = __expf(delta * A1);
        const float a2 = __expf(delta * A2);
        const float a3 = __expf(delta * A3);
        const float db = delta * uu;

        h0 = fmaf(a0, h0, db * Bv.x);
        h1 = fmaf(a1, h1, db * Bv.y);
        h2 = fmaf(a2, h2, db * Bv.z);
        h3 = fmaf(a3, h3, db * Bv.w);

        float ps = h0 * Cv.x;
        ps = fmaf(h1, Cv.y, ps);
        ps = fmaf(h2, Cv.z, ps);
        ps = fmaf(h3, Cv.w, ps);
        ps += __shfl_xor_sync(0xffffffffu, ps, 1);
        ps += __shfl_xor_sync(0xffffffffu, ps, 2);

        if (sub == 0) {
            float yv = (ps + uu * Dd) * S[xbase];
            __nv_bfloat16 hh = __float2bfloat16(yv);
            Yh[xbase] = hh;
            Yl[xbase] = __float2bfloat16(yv - __bfloat162float(hh));
        }
        xbase += DI;
        rbase += DS;
    }
}

// ---------------------------------------------------------------------------
extern "C" void kernel_launch(void* const* d_in, const int* in_sizes, int n_in,
                              void* d_out, int out_size)
{
    const float* x       = (const float*)d_in[0];
    const float* W_in    = (const float*)d_in[1];
    const float* W_delta = (const float*)d_in[2];
    const float* b_delta = (const float*)d_in[3];
    const float* W_B     = (const float*)d_in[4];
    const float* W_C     = (const float*)d_in[5];
    const float* A_log   = (const float*)d_in[6];
    const float* D_param = (const float*)d_in[7];
    const float* W_out   = (const float*)d_in[8];
    float* out = (float*)d_out;

    float *pU, *pS, *pDel, *pBM, *pCM;
    __nv_bfloat16 *pUh, *pUl, *pYh, *pYl, *pxh, *pxl;
    __nv_bfloat16 *pWih, *pWil, *pWdh, *pWdl, *pWoh, *pWol;
    cudaGetSymbolAddress((void**)&pU,   g_U);
    cudaGetSymbolAddress((void**)&pS,   g_S);
    cudaGetSymbolAddress((void**)&pDel, g_DELTA);
    cudaGetSymbolAddress((void**)&pBM,  g_BM);
    cudaGetSymbolAddress((void**)&pCM,  g_CM);
    cudaGetSymbolAddress((void**)&pUh,  g_Uh);
    cudaGetSymbolAddress((void**)&pUl,  g_Ul);
    cudaGetSymbolAddress((void**)&pYh,  g_Yh);
    cudaGetSymbolAddress((void**)&pYl,  g_Yl);
    cudaGetSymbolAddress((void**)&pxh,  g_xh);
    cudaGetSymbolAddress((void**)&pxl,  g_xl);
    cudaGetSymbolAddress((void**)&pWih, g_WinTh);
    cudaGetSymbolAddress((void**)&pWil, g_WinTl);
    cudaGetSymbolAddress((void**)&pWdh, g_WdTh);
    cudaGetSymbolAddress((void**)&pWdl, g_WdTl);
    cudaGetSymbolAddress((void**)&pWoh, g_WoTh);
    cudaGetSymbolAddress((void**)&pWol, g_WoTl);

    cudaFuncSetAttribute(tgemm<0>, cudaFuncAttributeMaxDynamicSharedMemorySize, SMEM_TOT);
    cudaFuncSetAttribute(tgemm<1>, cudaFuncAttributeMaxDynamicSharedMemorySize, SMEM_TOT);
    cudaFuncSetAttribute(tgemm<2>, cudaFuncAttributeMaxDynamicSharedMemorySize, SMEM_TOT);

    // prep: split x; transpose+split weights
    split_x_k<<<Mrows * DM / 1024, 256>>>(x, pxh, pxl);
    transp_split<<<dim3(2 * DI / 32, DM / 32), 256>>>(W_in,    pWih, pWil, DM, 2 * DI);
    transp_split<<<dim3(DI / 32,     DI / 32), 256>>>(W_delta, pWdh, pWdl, DI, DI);
    transp_split<<<dim3(DM / 32,     DI / 32), 256>>>(W_out,   pWoh, pWol, DI, DM);

    // 1) x @ W_in -> U (silu, fp32+bf16split) | S (silu)
    tgemm<0><<<dim3(2 * DI / 128, Mrows / 128), 256, SMEM_TOT>>>(
        pxh, pxl, pWih, pWil, DM, 2048, nullptr, pU, pS, pUh, pUl);

    // 2) Bm, Cm (SIMT)
    bc_k<<<Mrows / 8, 256>>>(pU, W_B, W_C, pBM, pCM);

    // 3) DELTA = softplus(U @ W_delta + b)
    tgemm<1><<<dim3(DI / 128, Mrows / 128), 256, SMEM_TOT>>>(
        pUh, pUl, pWdh, pWdl, DI, DI, b_delta, pDel, nullptr, nullptr, nullptr);

    // 4) selective scan -> Y (bf16 hi/lo)
    scan_k<<<Mrows * 4 / 64, 64>>>(pDel, pU, pS, pBM, pCM, A_log, D_param, pYh, pYl);

    // 5) out = Y @ W_out
    tgemm<2><<<dim3(DM / 128, Mrows / 128), 256, SMEM_TOT>>>(
        pYh, pYl, pWoh, pWol, DI, DM, nullptr, out, nullptr, nullptr, nullptr);
}

// round 6
// speedup vs baseline: 1.2785x; 1.2785x over previous
#include <cuda_runtime.h>
#include <cuda_fp16.h>
#include <cstdint>

#define DM 1024
#define DI 2048
#define DS 16
#define Mrows 4096
#define Lseq 2048

// ---------------- scratch (device globals; allocation-free) ----------------
__device__ float g_U[Mrows * DI];
__device__ float g_S[Mrows * DI];
__device__ float g_DELTA[Mrows * DI];
__device__ float g_BM[Mrows * DS];
__device__ float g_CM[Mrows * DS];
__device__ __half g_Uh[Mrows * DI], g_Ul[Mrows * DI];
__device__ __half g_Yh[Mrows * DI], g_Yl[Mrows * DI];
__device__ __half g_xh[Mrows * DM], g_xl[Mrows * DM];
__device__ __half g_WinT[2 * DI * DM];  // [4096][1024] fp16
__device__ __half g_WdT[DI * DI];       // [2048][2048]
__device__ __half g_WoT[DM * DI];       // [1024][2048]

// ---------------- helpers ----------------
__device__ __forceinline__ float siluf(float x) { return x / (1.0f + __expf(-x)); }
__device__ __forceinline__ float softplusf(float x) {
    return (x > 20.0f) ? x : log1pf(__expf(x));
}
__device__ __forceinline__ uint32_t smem_u32(const void* p) {
    uint32_t a;
    asm("{ .reg .u64 t; cvta.to.shared.u64 t, %1; cvt.u32.u64 %0, t; }" : "=r"(a) : "l"(p));
    return a;
}
__device__ __forceinline__ void cpa16(uint32_t s, const void* g) {
    asm volatile("cp.async.cg.shared.global [%0], [%1], 16;" :: "r"(s), "l"(g));
}
__device__ __forceinline__ void cpa_commit() { asm volatile("cp.async.commit_group;"); }

__device__ __forceinline__ void ldsm4(uint32_t* r, uint32_t addr) {
    asm volatile("ldmatrix.sync.aligned.m8n8.x4.shared.b16 {%0,%1,%2,%3}, [%4];"
                 : "=r"(r[0]), "=r"(r[1]), "=r"(r[2]), "=r"(r[3]) : "r"(addr));
}
__device__ __forceinline__ void mma16816h(float* d, const uint32_t* a, const uint32_t* b) {
    asm volatile(
        "mma.sync.aligned.m16n8k16.row.col.f32.f16.f16.f32 "
        "{%0,%1,%2,%3}, {%4,%5,%6,%7}, {%8,%9}, {%0,%1,%2,%3};\n"
        : "+f"(d[0]), "+f"(d[1]), "+f"(d[2]), "+f"(d[3])
        : "r"(a[0]), "r"(a[1]), "r"(a[2]), "r"(a[3]), "r"(b[0]), "r"(b[1]));
}

// SMEM: 3 tiles per stage (Ah, Al, B), each 128 rows x 32 fp16 (64B data),
// padded to 80B/row (16B-aligned; 80*r mod 128 distinct for r=0..7).
#define TPAD 80
#define TILE_B (128 * TPAD)          // 10240
#define STAGE_B (3 * TILE_B)         // 30720
#define NSTAGE 3
#define SMEM_TOT (NSTAGE * STAGE_B)  // 92160 -> 2 CTAs/SM

// ---------------------------------------------------------------------------
// load one K-chunk (32 cols) of 3 fp16 tiles (Ah, Al, B) into stage base sb.
// ---------------------------------------------------------------------------
__device__ __forceinline__ void load_chunk(
    const __half* __restrict__ Ah, const __half* __restrict__ Al,
    const __half* __restrict__ B,
    int m0, int n0, int kc, int Kdim, uint32_t sb, int tid, bool active)
{
    if (active) {
#pragma unroll
        for (int j = 0; j < 6; ++j) {
            const int g = j * 256 + tid;       // 0..1535
            const int tile = g >> 9;           // 0..2
            const int w = g & 511;
            const int row = w >> 2;
            const int col16 = w & 3;
            const __half* base = (tile == 0) ? Ah : (tile == 1) ? Al : B;
            const int r0 = (tile == 2) ? n0 : m0;
            const __half* src = base + (size_t)(r0 + row) * Kdim + kc + col16 * 8;
            cpa16(sb + (uint32_t)(tile * TILE_B + row * TPAD + col16 * 16),
                  (const void*)src);
        }
    }
    cpa_commit();
}

// ---------------------------------------------------------------------------
// HMMA fp16 asymmetric-split GEMM: C[M,N] = A[M,K] * B[N,K]^T  (fp32 accum)
// A as (Ah,Al) fp16 hi/lo; B single fp16. C ~= Ah*B + Al*B.
// Block 128x128, K-chunk 32, 3-stage cp.async, 8 warps (4m x 2n), 2 CTAs/SM.
// MODE 0: n0<2048 -> U=silu -> out0 fp32 + (obh,obl) fp16 split; else S -> out1
// MODE 1: softplus(c + bias[n]) -> out0
// MODE 2: plain -> out0
// ---------------------------------------------------------------------------
template <int MODE>
__global__ void __launch_bounds__(256, 2)
tgemm(const __half* __restrict__ Ah, const __half* __restrict__ Al,
      const __half* __restrict__ B,
      int Kdim, int ostride,
      const float* __restrict__ bias,
      float* __restrict__ out0, float* __restrict__ out1,
      __half* __restrict__ obh, __half* __restrict__ obl)
{
    extern __shared__ char smem[];
    const uint32_t sb = smem_u32(smem);

    const int tid  = threadIdx.x;
    const int lane = tid & 31;
    const int wid  = tid >> 5;
    const int wm   = wid & 3;   // 0..3 (m)
    const int wn   = wid >> 2;  // 0..1 (n)
    const int m0 = blockIdx.y * 128;
    const int n0 = blockIdx.x * 128;

    const uint32_t a_off =
        (uint32_t)(wm * 32 + (lane & 15)) * TPAD + (uint32_t)((lane >> 4) * 16);
    const int p = lane >> 3;
    const uint32_t b_off =
        (uint32_t)(wn * 64 + (p >> 1) * 8 + (lane & 7)) * TPAD + (uint32_t)((p & 1) * 16);

    float acc[2][8][4];
#pragma unroll
    for (int i = 0; i < 2; ++i)
#pragma unroll
        for (int j = 0; j < 8; ++j)
#pragma unroll
            for (int q = 0; q < 4; ++q) acc[i][j][q] = 0.0f;

    const int NC = Kdim >> 5;

    // prologue: prefetch chunks 0,1
#pragma unroll
    for (int s = 0; s < NSTAGE - 1; ++s)
        load_chunk(Ah, Al, B, m0, n0, s * 32, Kdim,
                   sb + (uint32_t)s * STAGE_B, tid, s < NC);

    for (int c = 0; c < NC; ++c) {
        asm volatile("cp.async.wait_group 1;" ::: "memory");
        __syncthreads();

        load_chunk(Ah, Al, B, m0, n0, (c + NSTAGE - 1) * 32, Kdim,
                   sb + (uint32_t)((c + NSTAGE - 1) % NSTAGE) * STAGE_B, tid,
                   (c + NSTAGE - 1) < NC);

        const uint32_t st = sb + (uint32_t)(c % NSTAGE) * STAGE_B;
        const uint32_t smAh = st;
        const uint32_t smAl = st + TILE_B;
        const uint32_t smB  = st + 2 * TILE_B;

#pragma unroll
        for (int k16 = 0; k16 < 2; ++k16) {
            const uint32_t kb = (uint32_t)(k16 * 32);
            uint32_t ah[2][4], al[2][4], bf[4][4];
#pragma unroll
            for (int mt = 0; mt < 2; ++mt) {
                ldsm4(ah[mt], smAh + kb + a_off + (uint32_t)(mt * 16 * TPAD));
                ldsm4(al[mt], smAl + kb + a_off + (uint32_t)(mt * 16 * TPAD));
            }
#pragma unroll
            for (int p2 = 0; p2 < 4; ++p2)
                ldsm4(bf[p2], smB + kb + b_off + (uint32_t)(p2 * 16 * TPAD));
#pragma unroll
            for (int mt = 0; mt < 2; ++mt) {
#pragma unroll
                for (int nt = 0; nt < 8; ++nt) {
                    const uint32_t* bb = &bf[nt >> 1][(nt & 1) * 2];
                    mma16816h(acc[mt][nt], ah[mt], bb);
                    mma16816h(acc[mt][nt], al[mt], bb);
                }
            }
        }
        __syncthreads();
    }

    // ---------------- epilogue ----------------
    const int g2 = lane >> 2;
    const int c2 = (lane & 3) * 2;
#pragma unroll
    for (int mt = 0; mt < 2; ++mt) {
        const int r0 = m0 + wm * 32 + mt * 16 + g2;
#pragma unroll
        for (int nt = 0; nt < 8; ++nt) {
            const int col = n0 + wn * 64 + nt * 8 + c2;
            float v0 = acc[mt][nt][0], v1 = acc[mt][nt][1];
            float v2 = acc[mt][nt][2], v3 = acc[mt][nt][3];

            if (MODE == 0) {
                v0 = siluf(v0); v1 = siluf(v1); v2 = siluf(v2); v3 = siluf(v3);
                if (n0 < 2048) {
                    *(float2*)(out0 + (size_t)r0 * 2048 + col)       = make_float2(v0, v1);
                    *(float2*)(out0 + (size_t)(r0 + 8) * 2048 + col) = make_float2(v2, v3);
                    __half2 h0, l0, h1, l1;
                    h0.x = __float2half(v0); h0.y = __float2half(v1);
                    l0.x = __float2half(v0 - __half2float(h0.x));
                    l0.y = __float2half(v1 - __half2float(h0.y));
                    h1.x = __float2half(v2); h1.y = __float2half(v3);
                    l1.x = __float2half(v2 - __half2float(h1.x));
                    l1.y = __float2half(v3 - __half2float(h1.y));
                    *(__half2*)(obh + (size_t)r0 * 2048 + col)       = h0;
                    *(__half2*)(obl + (size_t)r0 * 2048 + col)       = l0;
                    *(__half2*)(obh + (size_t)(r0 + 8) * 2048 + col) = h1;
                    *(__half2*)(obl + (size_t)(r0 + 8) * 2048 + col) = l1;
                } else {
                    const int cs = col - 2048;
                    *(float2*)(out1 + (size_t)r0 * 2048 + cs)       = make_float2(v0, v1);
                    *(float2*)(out1 + (size_t)(r0 + 8) * 2048 + cs) = make_float2(v2, v3);
                }
            } else if (MODE == 1) {
                const float b0 = bias[col], b1 = bias[col + 1];
                *(float2*)(out0 + (size_t)r0 * ostride + col) =
                    make_float2(softplusf(v0 + b0), softplusf(v1 + b1));
                *(float2*)(out0 + (size_t)(r0 + 8) * ostride + col) =
                    make_float2(softplusf(v2 + b0), softplusf(v3 + b1));
            } else {
                *(float2*)(out0 + (size_t)r0 * ostride + col)       = make_float2(v0, v1);
                *(float2*)(out0 + (size_t)(r0 + 8) * ostride + col) = make_float2(v2, v3);
            }
        }
    }
}

// ---------------------------------------------------------------------------
// weight transpose to fp16: in[K][N] fp32 -> oh [N][K] fp16
// ---------------------------------------------------------------------------
__global__ void __launch_bounds__(256)
transp_h(const float* __restrict__ in, __half* __restrict__ oh, int K, int N)
{
    __shared__ float t[32][33];
    const int n0 = blockIdx.x * 32, k0 = blockIdx.y * 32;
    const int tx = threadIdx.x & 31, ty = threadIdx.x >> 5;
#pragma unroll
    for (int i = 0; i < 32; i += 8)
        t[ty + i][tx] = in[(size_t)(k0 + ty + i) * N + n0 + tx];
    __syncthreads();
#pragma unroll
    for (int i = 0; i < 32; i += 8) {
        const int n = n0 + ty + i, k = k0 + tx;
        oh[(size_t)n * K + k] = __float2half(t[tx][ty + i]);
    }
}

// x -> fp16 hi/lo (elementwise)
__global__ void __launch_bounds__(256)
split_x_k(const float* __restrict__ x, __half* __restrict__ xh,
          __half* __restrict__ xl)
{
    const int i = blockIdx.x * 256 + threadIdx.x;
    float4 v = ((const float4*)x)[i];
    __half2 hh0, hh1, ll0, ll1;
    hh0.x = __float2half(v.x); hh0.y = __float2half(v.y);
    hh1.x = __float2half(v.z); hh1.y = __float2half(v.w);
    ll0.x = __float2half(v.x - __half2float(hh0.x));
    ll0.y = __float2half(v.y - __half2float(hh0.y));
    ll1.x = __float2half(v.z - __half2float(hh1.x));
    ll1.y = __float2half(v.w - __half2float(hh1.y));
    ((__half2*)xh)[2*i]   = hh0;
    ((__half2*)xh)[2*i+1] = hh1;
    ((__half2*)xl)[2*i]   = ll0;
    ((__half2*)xl)[2*i+1] = ll1;
}

// ---------------------------------------------------------------------------
// Bm = U @ W_B, Cm = U @ W_C (fp32 SIMT, K=2048, N=16 each)
// ---------------------------------------------------------------------------
__global__ void __launch_bounds__(256)
bc_k(const float* __restrict__ U,
     const float* __restrict__ WB, const float* __restrict__ WC,
     float* __restrict__ BMo, float* __restrict__ CMo)
{
    const int tid = threadIdx.x;
    const int n = tid & 31;
    const int r = tid >> 5;
    const int m = blockIdx.x * 8 + r;

    const float* Wp = (n < DS) ? (WB + n) : (WC + (n - DS));
    const float* Up = U + (size_t)m * DI;

    float acc = 0.0f;
#pragma unroll 8
    for (int k = 0; k < DI; ++k)
        acc = fmaf(Up[k], Wp[(size_t)k * DS], acc);

    if (n < DS) BMo[(size_t)m * DS + n] = acc;
    else        CMo[(size_t)m * DS + (n - DS)] = acc;
}

// ---------------------------------------------------------------------------
// Sequential selective scan; emits Y as fp16 hi/lo (input for final GEMM)
// ---------------------------------------------------------------------------
__global__ void __launch_bounds__(64)
scan_k(const float* __restrict__ DEL, const float* __restrict__ U,
       const float* __restrict__ S,
       const float* __restrict__ BMi, const float* __restrict__ CMi,
       const float* __restrict__ Alog, const float* __restrict__ Dp,
       __half* __restrict__ Yh, __half* __restrict__ Yl)
{
    const int tid = threadIdx.x;
    const int g = blockIdx.x * 16 + (tid >> 2);
    const int b = g >> 11;
    const int d = g & (DI - 1);
    const int sub = tid & 3;

    const float A0 = -__expf(Alog[d * DS + sub * 4 + 0]);
    const float A1 = -__expf(Alog[d * DS + sub * 4 + 1]);
    const float A2 = -__expf(Alog[d * DS + sub * 4 + 2]);
    const float A3 = -__expf(Alog[d * DS + sub * 4 + 3]);
    const float Dd = Dp[d];

    float h0 = 0.f, h1 = 0.f, h2 = 0.f, h3 = 0.f;
    size_t xbase = ((size_t)b * Lseq) * DI + d;
    size_t rbase = ((size_t)b * Lseq) * DS + sub * 4;

#pragma unroll 4
    for (int t = 0; t < Lseq; ++t) {
        const float delta = DEL[xbase];
        const float uu    = U[xbase];
        const float4 Bv = *(const float4*)(BMi + rbase);
        const float4 Cv = *(const float4*)(CMi + rbase);

        const float a0 = __expf(delta * A0);
        const float a1 = __expf(delta * A1);
        const float a2 = __expf(delta * A2);
        const float a3 = __expf(delta * A3);
        const float db = delta * uu;

        h0 = fmaf(a0, h0, db * Bv.x);
        h1 = fmaf(a1, h1, db * Bv.y);
        h2 = fmaf(a2, h2, db * Bv.z);
        h3 = fmaf(a3, h3, db * Bv.w);

        float ps = h0 * Cv.x;
        ps = fmaf(h1, Cv.y, ps);
        ps = fmaf(h2, Cv.z, ps);
        ps = fmaf(h3, Cv.w, ps);
        ps += __shfl_xor_sync(0xffffffffu, ps, 1);
        ps += __shfl_xor_sync(0xffffffffu, ps, 2);

        if (sub == 0) {
            float yv = (ps + uu * Dd) * S[xbase];
            __half hh = __float2half(yv);
            Yh[xbase] = hh;
            Yl[xbase] = __float2half(yv - __half2float(hh));
        }
        xbase += DI;
        rbase += DS;
    }
}

// ---------------------------------------------------------------------------
extern "C" void kernel_launch(void* const* d_in, const int* in_sizes, int n_in,
                              void* d_out, int out_size)
{
    const float* x       = (const float*)d_in[0];
    const float* W_in    = (const float*)d_in[1];
    const float* W_delta = (const float*)d_in[2];
    const float* b_delta = (const float*)d_in[3];
    const float* W_B     = (const float*)d_in[4];
    const float* W_C     = (const float*)d_in[5];
    const float* A_log   = (const float*)d_in[6];
    const float* D_param = (const float*)d_in[7];
    const float* W_out   = (const float*)d_in[8];
    float* out = (float*)d_out;

    float *pU, *pS, *pDel, *pBM, *pCM;
    __half *pUh, *pUl, *pYh, *pYl, *pxh, *pxl, *pWi, *pWd, *pWo;
    cudaGetSymbolAddress((void**)&pU,   g_U);
    cudaGetSymbolAddress((void**)&pS,   g_S);
    cudaGetSymbolAddress((void**)&pDel, g_DELTA);
    cudaGetSymbolAddress((void**)&pBM,  g_BM);
    cudaGetSymbolAddress((void**)&pCM,  g_CM);
    cudaGetSymbolAddress((void**)&pUh,  g_Uh);
    cudaGetSymbolAddress((void**)&pUl,  g_Ul);
    cudaGetSymbolAddress((void**)&pYh,  g_Yh);
    cudaGetSymbolAddress((void**)&pYl,  g_Yl);
    cudaGetSymbolAddress((void**)&pxh,  g_xh);
    cudaGetSymbolAddress((void**)&pxl,  g_xl);
    cudaGetSymbolAddress((void**)&pWi,  g_WinT);
    cudaGetSymbolAddress((void**)&pWd,  g_WdT);
    cudaGetSymbolAddress((void**)&pWo,  g_WoT);

    cudaFuncSetAttribute(tgemm<0>, cudaFuncAttributeMaxDynamicSharedMemorySize, SMEM_TOT);
    cudaFuncSetAttribute(tgemm<1>, cudaFuncAttributeMaxDynamicSharedMemorySize, SMEM_TOT);
    cudaFuncSetAttribute(tgemm<2>, cudaFuncAttributeMaxDynamicSharedMemorySize, SMEM_TOT);

    // prep: split x; transpose weights to fp16
    split_x_k<<<Mrows * DM / 1024, 256>>>(x, pxh, pxl);
    transp_h<<<dim3(2 * DI / 32, DM / 32), 256>>>(W_in,    pWi, DM, 2 * DI);
    transp_h<<<dim3(DI / 32,     DI / 32), 256>>>(W_delta, pWd, DI, DI);
    transp_h<<<dim3(DM / 32,     DI / 32), 256>>>(W_out,   pWo, DI, DM);

    // 1) x @ W_in -> U (silu, fp32+fp16split) | S (silu)
    tgemm<0><<<dim3(2 * DI / 128, Mrows / 128), 256, SMEM_TOT>>>(
        pxh, pxl, pWi, DM, 2048, nullptr, pU, pS, pUh, pUl);

    // 2) Bm, Cm (SIMT)
    bc_k<<<Mrows / 8, 256>>>(pU, W_B, W_C, pBM, pCM);

    // 3) DELTA = softplus(U @ W_delta + b)
    tgemm<1><<<dim3(DI / 128, Mrows / 128), 256, SMEM_TOT>>>(
        pUh, pUl, pWd, DI, DI, b_delta, pDel, nullptr, nullptr, nullptr);

    // 4) selective scan -> Y (fp16 hi/lo)
    scan_k<<<Mrows * 4 / 64, 64>>>(pDel, pU, pS, pBM, pCM, A_log, D_param, pYh, pYl);

    // 5) out = Y @ W_out
    tgemm<2><<<dim3(DM / 128, Mrows / 128), 256, SMEM_TOT>>>(
        pYh, pYl, pWo, DI, DM, nullptr, out, nullptr, nullptr, nullptr);
}